// round 11
// baseline (speedup 1.0000x reference)
#include <cuda_runtime.h>
#include <cuda_fp16.h>
#include <stdint.h>
#include <string.h>

#define K_DIM 2048
#define N_DIM 2048
#define TOPK  1024
#define BM 128
#define BN 128
#define BK 64
#define STAGES 3
#define TILE_BYTES (BM * BK * 2)          // 16 KB per operand tile
#define STAGE_BYTES (2 * TILE_BYTES)      // A + B = 32 KB
#define NITER (K_DIM / BK)                // 32
#define MASK_BLOCKS 2048
#define CONV_BLOCKS 16384                 // (16384*2048/8)/256

// Row-major fp16 scratch (device globals: allocation-free rule)
__device__ __align__(16) __half g_A[(size_t)16384 * K_DIM];
__device__ __align__(16) __half g_B[(size_t)N_DIM * K_DIM];

// ---------------------------------------------------------------------------
// PTX helpers (baseline sm_80+ features only: valid for compute_103 PTX)
// ---------------------------------------------------------------------------
__device__ __forceinline__ uint32_t smem_u32(const void* p) {
    uint32_t a;
    asm("{ .reg .u64 t; cvta.to.shared.u64 t, %1; cvt.u32.u64 %0, t; }" : "=r"(a) : "l"(p));
    return a;
}
__device__ __forceinline__ void cpa16(uint32_t dst, const void* src) {
    asm volatile("cp.async.cg.shared.global [%0], [%1], 16;" :: "r"(dst), "l"(src) : "memory");
}
__device__ __forceinline__ void cpa_commit() {
    asm volatile("cp.async.commit_group;" ::: "memory");
}
__device__ __forceinline__ void cpa_wait1() {
    asm volatile("cp.async.wait_group 1;" ::: "memory");
}
__device__ __forceinline__ void ldsm_x4(uint32_t (&r)[4], uint32_t addr) {
    asm volatile("ldmatrix.sync.aligned.m8n8.x4.shared.b16 {%0,%1,%2,%3}, [%4];"
                 : "=r"(r[0]), "=r"(r[1]), "=r"(r[2]), "=r"(r[3]) : "r"(addr));
}
__device__ __forceinline__ void mma_fp16(float (&c)[4], const uint32_t (&a)[4],
                                         uint32_t b0, uint32_t b1) {
    asm volatile(
        "mma.sync.aligned.m16n8k16.row.col.f32.f16.f16.f32 "
        "{%0,%1,%2,%3}, {%4,%5,%6,%7}, {%8,%9}, {%0,%1,%2,%3};"
        : "+f"(c[0]), "+f"(c[1]), "+f"(c[2]), "+f"(c[3])
        : "r"(a[0]), "r"(a[1]), "r"(a[2]), "r"(a[3]), "r"(b0), "r"(b1));
}

// ---------------------------------------------------------------------------
// Fused prep kernel (round-6 configuration: both paths lightweight, shared
// register budget stays ~26 regs so the memory-bound convert path keeps
// full occupancy):
//   blocks [0, MASK_BLOCKS):   per-row exact top-k radix select -> g_B fp16
//   blocks [MASK_BLOCKS, ...): x fp32 -> fp16 into g_A
// ---------------------------------------------------------------------------
__global__ __launch_bounds__(256) void prep_kernel(const float* __restrict__ w,
                                                   const float* __restrict__ x) {
    __shared__ unsigned int bits[K_DIM];
    __shared__ unsigned int hA[256];
    __shared__ unsigned int hBuf[256];
    __shared__ unsigned int s_prefix, s_kwant, s_cnt_gt;

    const int tid = threadIdx.x;

    if (blockIdx.x >= MASK_BLOCKS) {
        // ---- convert path ----
        const size_t t = (size_t)(blockIdx.x - MASK_BLOCKS) * 256 + tid;
        const size_t base = t * 8;
        const float4* src = (const float4*)(x + base);
        float4 v0 = src[0], v1 = src[1];

        __half2 h0 = __floats2half2_rn(v0.x, v0.y);
        __half2 h1 = __floats2half2_rn(v0.z, v0.w);
        __half2 h2 = __floats2half2_rn(v1.x, v1.y);
        __half2 h3 = __floats2half2_rn(v1.z, v1.w);

        uint32_t p0, p1, p2, p3;
        memcpy(&p0, &h0, 4); memcpy(&p1, &h1, 4);
        memcpy(&p2, &h2, 4); memcpy(&p3, &h3, 4);
        *(uint4*)(g_A + base) = make_uint4(p0, p1, p2, p3);
        return;
    }

    // ---- mask path ----
    const int row = blockIdx.x;
    const float* wr = w + (size_t)row * K_DIM;

    for (int i = tid; i < K_DIM; i += 256)
        bits[i] = __float_as_uint(wr[i]) & 0x7FFFFFFFu;
    if (tid == 0) s_cnt_gt = 0;
    __syncthreads();

    unsigned int prefix = 0, kwant = TOPK;
    #pragma unroll
    for (int pass = 3; pass >= 0; --pass) {
        const int shift = pass * 8;
        hA[tid] = 0;
        __syncthreads();
        if (pass == 3) {
            for (int i = tid; i < K_DIM; i += 256)
                atomicAdd(&hA[(bits[i] >> shift) & 0xFFu], 1u);
        } else {
            const unsigned int hi_mask = 0xFFFFFFFFu << (shift + 8);
            for (int i = tid; i < K_DIM; i += 256) {
                const unsigned int b = bits[i];
                if ((b & hi_mask) == (prefix & hi_mask))
                    atomicAdd(&hA[(b >> shift) & 0xFFu], 1u);
            }
        }
        __syncthreads();

        // Parallel inclusive suffix scan: S(i) = sum_{j>=i} hist[j]
        unsigned int* cur = hA;
        unsigned int* nxt = hBuf;
        unsigned int v = cur[tid];
        #pragma unroll
        for (int step = 1; step < 256; step <<= 1) {
            unsigned int add = (tid + step < 256) ? cur[tid + step] : 0u;
            v += add;
            nxt[tid] = v;
            unsigned int* tmp = cur; cur = nxt; nxt = tmp;
            __syncthreads();
        }
        const unsigned int S_next = (tid == 255) ? 0u : cur[tid + 1];
        if (v >= kwant && S_next < kwant) {
            s_prefix = prefix | ((unsigned int)tid << shift);
            s_kwant  = kwant - S_next;
        }
        __syncthreads();
        prefix = s_prefix;
        kwant  = s_kwant;
        __syncthreads();
    }
    const unsigned int thresh = prefix;

    unsigned int local_gt = 0;
    for (int i = tid; i < K_DIM; i += 256)
        if (bits[i] > thresh) local_gt++;
    atomicAdd(&s_cnt_gt, local_gt);
    __syncthreads();
    const unsigned int need_eq = TOPK - s_cnt_gt;

    for (int i = tid; i < K_DIM; i += 256) {
        const unsigned int b = bits[i];
        float val = 0.0f;
        if (b > thresh) {
            val = wr[i];
        } else if (b == thresh) {
            unsigned int rr = 0;
            for (int j = 0; j < i; ++j) rr += (bits[j] == thresh);
            if (rr < need_eq) val = wr[i];
        }
        g_B[(size_t)row * K_DIM + i] = __float2half_rn(val);
    }
}

// ---------------------------------------------------------------------------
// GEMM: pipelined mma.sync fp16, K = 2048. Round-10 configuration:
// 128x128 tile/CTA, 256 thr (2x4 warps of 64x32), 3-stage cp.async pipeline,
// SINGLE barrier per K-iteration (stage overwritten at iter `it` was consumed
// at it-1, already ordered by the top-of-iter barrier).
// ---------------------------------------------------------------------------
__device__ __forceinline__ void load_stage(uint32_t sbase, int st, int kc,
                                           int m0, int n0, int tid) {
    const uint32_t sA = sbase + st * STAGE_BYTES;
    const uint32_t sB = sA + TILE_BYTES;
    #pragma unroll
    for (int u = 0; u < 4; ++u) {
        const int f   = tid + u * 256;
        const int row = f >> 3;
        const int ch  = f & 7;
        const uint32_t so = (uint32_t)(row * 8 + (ch ^ (row & 7))) * 16u;
        cpa16(sA + so, g_A + (size_t)(m0 + row) * K_DIM + kc + ch * 8);
        cpa16(sB + so, g_B + (size_t)(n0 + row) * K_DIM + kc + ch * 8);
    }
}

__global__ void __launch_bounds__(256, 2) gemm_mma(const float* __restrict__ bias,
                                                   float* __restrict__ y) {
    extern __shared__ unsigned char dyn_smem[];
    const uint32_t sbase = smem_u32(dyn_smem);

    const int tid  = threadIdx.x;
    const int wid  = tid >> 5;
    const int lane = tid & 31;
    const int m_tile = blockIdx.x >> 4;
    const int n_tile = blockIdx.x & 15;
    const int m0 = m_tile * BM;
    const int n0 = n_tile * BN;

    const int wm = wid >> 2;          // 0..1
    const int wn = wid & 3;           // 0..3
    const int lr = lane & 15;         // ldmatrix row within 16
    const int lc = lane >> 4;         // ldmatrix k-chunk selector
    const int arow0 = wm * 64 + lr;   // hoisted row bases
    const int brow0 = wn * 32 + lr;

    float acc[4][4][4];
    #pragma unroll
    for (int i = 0; i < 4; ++i)
        #pragma unroll
        for (int j = 0; j < 4; ++j)
            #pragma unroll
            for (int r = 0; r < 4; ++r) acc[i][j][r] = 0.0f;

    load_stage(sbase, 0, 0, m0, n0, tid); cpa_commit();
    load_stage(sbase, 1, BK, m0, n0, tid); cpa_commit();

    for (int it = 0; it < NITER; ++it) {
        const int st = it % STAGES;
        cpa_wait1();          // stage `it` landed (1 newer group pending)
        __syncthreads();      // loads visible; compute of it-1 finished, so
                              // stage (it+2)%3 == (it-1)%3 is free to overwrite

        if (it + 2 < NITER) load_stage(sbase, (it + 2) % STAGES, (it + 2) * BK, m0, n0, tid);
        cpa_commit();

        const uint32_t sA = sbase + st * STAGE_BYTES;
        const uint32_t sB = sA + TILE_BYTES;

        #pragma unroll
        for (int ks = 0; ks < 4; ++ks) {
            const int ch = ks * 2 + lc;
            uint32_t a[4][4], b[2][4];
            #pragma unroll
            for (int ms = 0; ms < 4; ++ms) {
                const int row = arow0 + ms * 16;
                ldsm_x4(a[ms], sA + (uint32_t)(row * 8 + (ch ^ (row & 7))) * 16u);
            }
            #pragma unroll
            for (int bs = 0; bs < 2; ++bs) {
                const int row = brow0 + bs * 16;
                ldsm_x4(b[bs], sB + (uint32_t)(row * 8 + (ch ^ (row & 7))) * 16u);
            }
            #pragma unroll
            for (int ms = 0; ms < 4; ++ms)
                #pragma unroll
                for (int nb = 0; nb < 4; ++nb)
                    mma_fp16(acc[ms][nb], a[ms], b[nb >> 1][nb & 1], b[nb >> 1][2 + (nb & 1)]);
        }
        // no trailing barrier: next iteration's top barrier provides ordering
    }

    // Epilogue: bias add + float2 stores
    const int ln4 = lane & 3;
    const int lg  = lane >> 2;
    float2 bv[4];
    #pragma unroll
    for (int nb = 0; nb < 4; ++nb) {
        const int c = n0 + wn * 32 + nb * 8 + ln4 * 2;
        bv[nb].x = __ldg(bias + c);
        bv[nb].y = __ldg(bias + c + 1);
    }
    #pragma unroll
    for (int ms = 0; ms < 4; ++ms) {
        const int r0 = m0 + wm * 64 + ms * 16 + lg;
        #pragma unroll
        for (int nb = 0; nb < 4; ++nb) {
            const int c = n0 + wn * 32 + nb * 8 + ln4 * 2;
            float2 o0, o1;
            o0.x = acc[ms][nb][0] + bv[nb].x;
            o0.y = acc[ms][nb][1] + bv[nb].y;
            o1.x = acc[ms][nb][2] + bv[nb].x;
            o1.y = acc[ms][nb][3] + bv[nb].y;
            *(float2*)(y + (size_t)r0 * N_DIM + c)       = o0;
            *(float2*)(y + (size_t)(r0 + 8) * N_DIM + c) = o1;
        }
    }
}

// ---------------------------------------------------------------------------
extern "C" void kernel_launch(void* const* d_in, const int* in_sizes, int n_in,
                              void* d_out, int out_size) {
    const float* x    = (const float*)d_in[0];   // [8,2048,2048]
    const float* w    = (const float*)d_in[1];   // [2048,2048]
    const float* bias = (const float*)d_in[2];   // [2048]
    float* y = (float*)d_out;

    const int M = in_sizes[0] / K_DIM;           // 16384

    cudaFuncSetAttribute(gemm_mma, cudaFuncAttributeMaxDynamicSharedMemorySize,
                         STAGES * STAGE_BYTES);

    prep_kernel<<<MASK_BLOCKS + CONV_BLOCKS, 256>>>(w, x);

    const int grid = (M / BM) * (N_DIM / BN);    // 128 * 16 = 2048
    gemm_mma<<<grid, 256, STAGES * STAGE_BYTES>>>(bias, y);
}

// round 12
// speedup vs baseline: 1.5772x; 1.5772x over previous
#include <cuda_runtime.h>
#include <cuda_fp16.h>
#include <stdint.h>
#include <string.h>

#define K_DIM 2048
#define N_DIM 2048
#define TOPK  1024
#define BM 128
#define BN 128
#define BK 64
#define STAGES 3
#define TILE_BYTES (BM * BK * 2)          // 16 KB per operand tile
#define STAGE_BYTES (2 * TILE_BYTES)      // A + B = 32 KB
#define NITER (K_DIM / BK)                // 32
#define MASK_BLOCKS 2048
#define CONV_BLOCKS 16384                 // (16384*2048/8)/256

// Row-major fp16 scratch (device globals: allocation-free rule)
__device__ __align__(16) __half g_A[(size_t)16384 * K_DIM];
__device__ __align__(16) __half g_B[(size_t)N_DIM * K_DIM];

// ---------------------------------------------------------------------------
// PTX helpers (baseline sm_80+ features only: valid for compute_103 PTX)
// ---------------------------------------------------------------------------
__device__ __forceinline__ uint32_t smem_u32(const void* p) {
    uint32_t a;
    asm("{ .reg .u64 t; cvta.to.shared.u64 t, %1; cvt.u32.u64 %0, t; }" : "=r"(a) : "l"(p));
    return a;
}
__device__ __forceinline__ void cpa16(uint32_t dst, const void* src) {
    asm volatile("cp.async.cg.shared.global [%0], [%1], 16;" :: "r"(dst), "l"(src) : "memory");
}
__device__ __forceinline__ void cpa_commit() {
    asm volatile("cp.async.commit_group;" ::: "memory");
}
__device__ __forceinline__ void cpa_wait1() {
    asm volatile("cp.async.wait_group 1;" ::: "memory");
}
__device__ __forceinline__ void ldsm_x4(uint32_t (&r)[4], uint32_t addr) {
    asm volatile("ldmatrix.sync.aligned.m8n8.x4.shared.b16 {%0,%1,%2,%3}, [%4];"
                 : "=r"(r[0]), "=r"(r[1]), "=r"(r[2]), "=r"(r[3]) : "r"(addr));
}
__device__ __forceinline__ void mma_fp16(float (&c)[4], const uint32_t (&a)[4],
                                         uint32_t b0, uint32_t b1) {
    asm volatile(
        "mma.sync.aligned.m16n8k16.row.col.f32.f16.f16.f32 "
        "{%0,%1,%2,%3}, {%4,%5,%6,%7}, {%8,%9}, {%0,%1,%2,%3};"
        : "+f"(c[0]), "+f"(c[1]), "+f"(c[2]), "+f"(c[3])
        : "r"(a[0]), "r"(a[1]), "r"(a[2]), "r"(a[3]), "r"(b0), "r"(b1));
}

// ---------------------------------------------------------------------------
// Fused prep kernel (lightweight on both paths so the memory-bound convert
// path keeps full occupancy):
//   blocks [0, MASK_BLOCKS):   per-row exact top-k radix select -> g_B fp16
//   blocks [MASK_BLOCKS, ...): x fp32 -> fp16 into g_A
// ---------------------------------------------------------------------------
__global__ __launch_bounds__(256) void prep_kernel(const float* __restrict__ w,
                                                   const float* __restrict__ x) {
    __shared__ unsigned int bits[K_DIM];
    __shared__ unsigned int hA[256];
    __shared__ unsigned int hBuf[256];
    __shared__ unsigned int s_prefix, s_kwant, s_cnt_gt, s_cnt_eq;

    const int tid = threadIdx.x;

    if (blockIdx.x >= MASK_BLOCKS) {
        // ---- convert path ----
        const size_t t = (size_t)(blockIdx.x - MASK_BLOCKS) * 256 + tid;
        const size_t base = t * 8;
        const float4* src = (const float4*)(x + base);
        float4 v0 = src[0], v1 = src[1];

        __half2 h0 = __floats2half2_rn(v0.x, v0.y);
        __half2 h1 = __floats2half2_rn(v0.z, v0.w);
        __half2 h2 = __floats2half2_rn(v1.x, v1.y);
        __half2 h3 = __floats2half2_rn(v1.z, v1.w);

        uint32_t p0, p1, p2, p3;
        memcpy(&p0, &h0, 4); memcpy(&p1, &h1, 4);
        memcpy(&p2, &h2, 4); memcpy(&p3, &h3, 4);
        *(uint4*)(g_A + base) = make_uint4(p0, p1, p2, p3);
        return;
    }

    // ---- mask path ----
    const int row = blockIdx.x;
    const float* wr = w + (size_t)row * K_DIM;

    for (int i = tid; i < K_DIM; i += 256)
        bits[i] = __float_as_uint(wr[i]) & 0x7FFFFFFFu;
    if (tid == 0) { s_cnt_gt = 0; s_cnt_eq = 0; }
    __syncthreads();

    unsigned int prefix = 0, kwant = TOPK;
    #pragma unroll
    for (int pass = 3; pass >= 0; --pass) {
        const int shift = pass * 8;
        hA[tid] = 0;
        __syncthreads();
        if (pass == 3) {
            for (int i = tid; i < K_DIM; i += 256)
                atomicAdd(&hA[(bits[i] >> shift) & 0xFFu], 1u);
        } else {
            const unsigned int hi_mask = 0xFFFFFFFFu << (shift + 8);
            for (int i = tid; i < K_DIM; i += 256) {
                const unsigned int b = bits[i];
                if ((b & hi_mask) == (prefix & hi_mask))
                    atomicAdd(&hA[(b >> shift) & 0xFFu], 1u);
            }
        }
        __syncthreads();

        // Parallel inclusive suffix scan: S(i) = sum_{j>=i} hist[j]
        unsigned int* cur = hA;
        unsigned int* nxt = hBuf;
        unsigned int v = cur[tid];
        #pragma unroll
        for (int step = 1; step < 256; step <<= 1) {
            unsigned int add = (tid + step < 256) ? cur[tid + step] : 0u;
            v += add;
            nxt[tid] = v;
            unsigned int* tmp = cur; cur = nxt; nxt = tmp;
            __syncthreads();
        }
        const unsigned int S_next = (tid == 255) ? 0u : cur[tid + 1];
        if (v >= kwant && S_next < kwant) {
            s_prefix = prefix | ((unsigned int)tid << shift);
            s_kwant  = kwant - S_next;
        }
        __syncthreads();
        prefix = s_prefix;
        kwant  = s_kwant;
        __syncthreads();
    }
    const unsigned int thresh = prefix;

    unsigned int local_gt = 0, local_eq = 0;
    for (int i = tid; i < K_DIM; i += 256) {
        local_gt += (bits[i] > thresh);
        local_eq += (bits[i] == thresh);
    }
    if (local_gt) atomicAdd(&s_cnt_gt, local_gt);
    if (local_eq) atomicAdd(&s_cnt_eq, local_eq);
    __syncthreads();
    const unsigned int need_eq = TOPK - s_cnt_gt;
    const bool keep_all_eq = (s_cnt_eq == need_eq);   // no true fp ties (common)

    for (int i = tid; i < K_DIM; i += 256) {
        const unsigned int b = bits[i];
        float val = 0.0f;
        if (b > thresh) {
            val = wr[i];
        } else if (b == thresh) {
            if (keep_all_eq) {
                val = wr[i];
            } else {
                // rare duplicate-bit-pattern case: first-index-first ranking
                unsigned int rr = 0;
                for (int j = 0; j < i; ++j) rr += (bits[j] == thresh);
                if (rr < need_eq) val = wr[i];
            }
        }
        g_B[(size_t)row * K_DIM + i] = __float2half_rn(val);
    }
}

// ---------------------------------------------------------------------------
// GEMM: pipelined mma.sync fp16, K = 2048.
// 128x128 tile/CTA, 256 thr (2x4 warps of 64x32), 3-stage cp.async pipeline,
// SINGLE barrier per K-iteration (stage overwritten at iter `it` was consumed
// at it-1, already ordered by the top-of-iter barrier).
// ---------------------------------------------------------------------------
__device__ __forceinline__ void load_stage(uint32_t sbase, int st, int kc,
                                           int m0, int n0, int tid) {
    const uint32_t sA = sbase + st * STAGE_BYTES;
    const uint32_t sB = sA + TILE_BYTES;
    #pragma unroll
    for (int u = 0; u < 4; ++u) {
        const int f   = tid + u * 256;
        const int row = f >> 3;
        const int ch  = f & 7;
        const uint32_t so = (uint32_t)(row * 8 + (ch ^ (row & 7))) * 16u;
        cpa16(sA + so, g_A + (size_t)(m0 + row) * K_DIM + kc + ch * 8);
        cpa16(sB + so, g_B + (size_t)(n0 + row) * K_DIM + kc + ch * 8);
    }
}

__global__ void __launch_bounds__(256, 2) gemm_mma(const float* __restrict__ bias,
                                                   float* __restrict__ y) {
    extern __shared__ unsigned char dyn_smem[];
    const uint32_t sbase = smem_u32(dyn_smem);

    const int tid  = threadIdx.x;
    const int wid  = tid >> 5;
    const int lane = tid & 31;
    const int m_tile = blockIdx.x >> 4;
    const int n_tile = blockIdx.x & 15;
    const int m0 = m_tile * BM;
    const int n0 = n_tile * BN;

    const int wm = wid >> 2;          // 0..1
    const int wn = wid & 3;           // 0..3
    const int lr = lane & 15;         // ldmatrix row within 16
    const int lc = lane >> 4;         // ldmatrix k-chunk selector
    const int arow0 = wm * 64 + lr;
    const int brow0 = wn * 32 + lr;

    float acc[4][4][4];
    #pragma unroll
    for (int i = 0; i < 4; ++i)
        #pragma unroll
        for (int j = 0; j < 4; ++j)
            #pragma unroll
            for (int r = 0; r < 4; ++r) acc[i][j][r] = 0.0f;

    load_stage(sbase, 0, 0, m0, n0, tid); cpa_commit();
    load_stage(sbase, 1, BK, m0, n0, tid); cpa_commit();

    for (int it = 0; it < NITER; ++it) {
        const int st = it % STAGES;
        cpa_wait1();          // stage `it` landed (1 newer group pending)
        __syncthreads();      // loads visible; compute of it-1 finished, so
                              // stage (it+2)%3 == (it-1)%3 is free to overwrite

        if (it + 2 < NITER) load_stage(sbase, (it + 2) % STAGES, (it + 2) * BK, m0, n0, tid);
        cpa_commit();

        const uint32_t sA = sbase + st * STAGE_BYTES;
        const uint32_t sB = sA + TILE_BYTES;

        #pragma unroll
        for (int ks = 0; ks < 4; ++ks) {
            const int ch = ks * 2 + lc;
            uint32_t a[4][4], b[2][4];
            #pragma unroll
            for (int ms = 0; ms < 4; ++ms) {
                const int row = arow0 + ms * 16;
                ldsm_x4(a[ms], sA + (uint32_t)(row * 8 + (ch ^ (row & 7))) * 16u);
            }
            #pragma unroll
            for (int bs = 0; bs < 2; ++bs) {
                const int row = brow0 + bs * 16;
                ldsm_x4(b[bs], sB + (uint32_t)(row * 8 + (ch ^ (row & 7))) * 16u);
            }
            #pragma unroll
            for (int ms = 0; ms < 4; ++ms)
                #pragma unroll
                for (int nb = 0; nb < 4; ++nb)
                    mma_fp16(acc[ms][nb], a[ms], b[nb >> 1][nb & 1], b[nb >> 1][2 + (nb & 1)]);
        }
        // no trailing barrier: next iteration's top barrier provides ordering
    }

    // Epilogue: bias add + float2 stores
    const int ln4 = lane & 3;
    const int lg  = lane >> 2;
    float2 bv[4];
    #pragma unroll
    for (int nb = 0; nb < 4; ++nb) {
        const int c = n0 + wn * 32 + nb * 8 + ln4 * 2;
        bv[nb].x = __ldg(bias + c);
        bv[nb].y = __ldg(bias + c + 1);
    }
    #pragma unroll
    for (int ms = 0; ms < 4; ++ms) {
        const int r0 = m0 + wm * 64 + ms * 16 + lg;
        #pragma unroll
        for (int nb = 0; nb < 4; ++nb) {
            const int c = n0 + wn * 32 + nb * 8 + ln4 * 2;
            float2 o0, o1;
            o0.x = acc[ms][nb][0] + bv[nb].x;
            o0.y = acc[ms][nb][1] + bv[nb].y;
            o1.x = acc[ms][nb][2] + bv[nb].x;
            o1.y = acc[ms][nb][3] + bv[nb].y;
            *(float2*)(y + (size_t)r0 * N_DIM + c)       = o0;
            *(float2*)(y + (size_t)(r0 + 8) * N_DIM + c) = o1;
        }
    }
}

// ---------------------------------------------------------------------------
extern "C" void kernel_launch(void* const* d_in, const int* in_sizes, int n_in,
                              void* d_out, int out_size) {
    const float* x    = (const float*)d_in[0];   // [8,2048,2048]
    const float* w    = (const float*)d_in[1];   // [2048,2048]
    const float* bias = (const float*)d_in[2];   // [2048]
    float* y = (float*)d_out;

    const int M = in_sizes[0] / K_DIM;           // 16384

    cudaFuncSetAttribute(gemm_mma, cudaFuncAttributeMaxDynamicSharedMemorySize,
                         STAGES * STAGE_BYTES);

    prep_kernel<<<MASK_BLOCKS + CONV_BLOCKS, 256>>>(w, x);

    const int grid = (M / BM) * (N_DIM / BN);    // 128 * 16 = 2048
    gemm_mma<<<grid, 256, STAGES * STAGE_BYTES>>>(bias, y);
}